// round 16
// baseline (speedup 1.0000x reference)
#include <cuda_runtime.h>
#include <mma.h>
#include <math.h>
#include <stdint.h>

using namespace nvcuda;

#define B_    1024
#define NTR_  127
#define NRED  63
#define OUT0SZ (NTR_ * B_ * 3)
#define SMEMB 55296   // parallel tgemm: 3 stages x (64x36 + 64x36) x4B ; persist: 2 x 6912 floats
#define G_    128     // persistent grid size

// ---------------- Device scratch ----------------
__device__ float g_buf [(size_t)B_ * NTR_ * 256];   // full precision
__device__ float g_bufR[(size_t)B_ * NTR_ * 256];   // tf32-rounded
__device__ float g_embedR[(size_t)50000 * 256];
__device__ float g_P12[(size_t)66 * B_ * 2048];
__device__ float g_P3 [(size_t)3 * B_ * 1024];
__device__ float g_Prw[(size_t)62 * B_ * 1280];
__device__ float g_Plw[(size_t)B_ * 1280];
__device__ float g_Hred[(size_t)NRED * B_ * 256];
__device__ float g_Cred[(size_t)NRED * B_ * 256];
__device__ float g_th[2 * B_ * 256];
__device__ float g_tc[B_ * 256];
__device__ float g_lstmin[(size_t)B_ * 1280];
__device__ float g_Wc12 [2048 * 256];
__device__ float g_W3i  [1024 * 256];
__device__ float g_WtrkA[1024 * 512];
__device__ float g_WtrkB[1024 * 512];
__device__ float g_WredA[1280 * 512];
__device__ float g_WredB[1280 * 512];
__device__ float g_Rw   [1280 * 256];
__device__ float g_Lw   [1280 * 256];
__device__ float g_Win  [256 * 256];
__device__ float g_btrk [1024];
__device__ int   g_cmap [132];

// persistent-kernel metadata + barrier
struct TrkMeta { const float* seg0; long s0s; const float* W;
                 const float* addA; const float* addB; int addBld; int isred; };
struct RedMeta { const float* sg; long sgs; const float* W; const float* addA;
                 const float* lc; int lcs; const float* rc; int rcs;
                 float* Hr; float* Cr; int r; };
__device__ TrkMeta g_tm[127];
__device__ RedMeta g_rm[127];
__device__ unsigned g_barc;

__device__ __forceinline__ uint32_t smem_u32(const void* p) {
    uint32_t a;
    asm("{ .reg .u64 t; cvta.to.shared.u64 t, %1; cvt.u32.u64 %0, t; }" : "=r"(a) : "l"(p));
    return a;
}
__device__ __forceinline__ float sigf(float x) { return 1.0f / (1.0f + expf(-x)); }
__device__ __forceinline__ float rnd32(float x) {
    float y; asm("cvt.rna.tf32.f32 %0,%1;" : "=f"(y) : "f"(x)); return y;
}
__device__ __forceinline__ void cp16(uint32_t d, const float* s) {
    asm volatile("cp.async.cg.shared.global [%0], [%1], 16;" :: "r"(d), "l"(s) : "memory");
}

__device__ __forceinline__ void grid_bar(unsigned& goal) {
    __syncthreads();
    if (threadIdx.x == 0) {
        __threadfence();
        atomicAdd(&g_barc, 1u);
        while (*(volatile unsigned*)&g_barc < goal) __nanosleep(32);
        __threadfence();
    }
    __syncthreads();
    goal += G_;
}

__global__ void reset_bar_k() { g_barc = 0u; }

// =====================================================================
// Persistent-kernel GEMM tile: 64(M) x 128(N), K=512 (seg0 256 | th 256),
// 256 threads, 2-stage cp.async.cg double buffer.
// MODE 0: tracker — fused interleaved-gate LSTM cell epilogue
// MODE 1: reduce  — lstmin = acc + bias + addA
// =====================================================================
template<int MODE>
__device__ __forceinline__ void gemm_tile(
    float* dsm, const int tid, const int mt, const int nt,
    const float* __restrict__ W,
    const float* __restrict__ seg0, const long s0s,
    const float* __restrict__ th,
    const float* __restrict__ bias,
    const float* __restrict__ addA, const int adAld,
    const float* __restrict__ addB, const int adBld,
    float* __restrict__ tcio, float* __restrict__ thout,
    float* __restrict__ lstmin)
{
    const uint32_t uS = smem_u32(dsm);
    const int r4 = tid >> 2, c8 = (tid & 3) << 3;
    const int rB = tid >> 1, cB = (tid & 1) << 4;
    const long mA = (long)mt * 64 + r4;
    const float* segrow = seg0 + mA * s0s + c8;
    const float* throw_ = th + mA * 256 + c8;
    const float* wrow = W + ((size_t)nt * 2 + (tid >> 7)) * 16 * 2048
                          + (size_t)(rB & 63) * 32 + cB;

    auto ldst = [&](int ch, int st) {
        const uint32_t base = uS + (uint32_t)st * (6912u * 4u);
        const float* sa = (ch < 8) ? (segrow + ch * 32) : (throw_ + (ch - 8) * 32);
        const uint32_t dA = base + (uint32_t)(r4 * 36 + c8) * 4;
        cp16(dA, sa); cp16(dA + 16, sa + 4);
        const float* sb = wrow + (size_t)ch * 2048;
        const uint32_t dB = base + 9216u + (uint32_t)(rB * 36 + cB) * 4;
        cp16(dB, sb); cp16(dB + 16, sb + 4); cp16(dB + 32, sb + 8); cp16(dB + 48, sb + 12);
        asm volatile("cp.async.commit_group;" ::: "memory");
    };

    wmma::fragment<wmma::accumulator, 16, 16, 8, float> fc[2][2];
    #pragma unroll
    for (int i = 0; i < 2; i++)
        #pragma unroll
        for (int j = 0; j < 2; j++) wmma::fill_fragment(fc[i][j], 0.0f);

    const int wid = tid >> 5, wm = wid & 1, wn = wid >> 1;

    ldst(0, 0);
    for (int ch = 0; ch < 16; ch++) {
        if (ch + 1 < 16) {
            ldst(ch + 1, (ch + 1) & 1);
            asm volatile("cp.async.wait_group 1;" ::: "memory");
        } else {
            asm volatile("cp.async.wait_group 0;" ::: "memory");
        }
        __syncthreads();
        const float* As = dsm + (ch & 1) * 6912;
        const float* Bs = As + 2304;
        #pragma unroll
        for (int ks = 0; ks < 4; ks++) {
            wmma::fragment<wmma::matrix_a, 16, 16, 8, wmma::precision::tf32, wmma::row_major> fa[2];
            wmma::fragment<wmma::matrix_b, 16, 16, 8, wmma::precision::tf32, wmma::col_major> fb[2];
            #pragma unroll
            for (int mi = 0; mi < 2; mi++)
                wmma::load_matrix_sync(fa[mi], As + (wm * 32 + mi * 16) * 36 + ks * 8, 36);
            #pragma unroll
            for (int nj = 0; nj < 2; nj++)
                wmma::load_matrix_sync(fb[nj], Bs + (wn * 32 + nj * 16) * 36 + ks * 8, 36);
            #pragma unroll
            for (int mi = 0; mi < 2; mi++)
                #pragma unroll
                for (int nj = 0; nj < 2; nj++)
                    wmma::mma_sync(fc[mi][nj], fa[mi], fb[nj], fc[mi][nj]);
        }
        __syncthreads();
    }

    float* Cs = dsm;   // 64 x 132 staging
    #pragma unroll
    for (int mi = 0; mi < 2; mi++)
        #pragma unroll
        for (int nj = 0; nj < 2; nj++)
            wmma::store_matrix_sync(Cs + (wm * 32 + mi * 16) * 132 + wn * 32 + nj * 16,
                                    fc[mi][nj], 132, wmma::mem_row_major);
    __syncthreads();

    for (int idx = tid; idx < 2048; idx += 256) {
        const int row = idx >> 5, q = idx & 31;
        float4 v = *(const float4*)&Cs[row * 132 + q * 4];
        const int col = nt * 128 + q * 4;
        const long m = (long)mt * 64 + row;
        v.x += bias[col]; v.y += bias[col + 1]; v.z += bias[col + 2]; v.w += bias[col + 3];
        {
            const float4 a = *(const float4*)(addA + (size_t)m * adAld + col);
            v.x += a.x; v.y += a.y; v.z += a.z; v.w += a.w;
        }
        if (MODE == 0) {
            const float4 a2 = *(const float4*)(addB + (size_t)m * adBld + col);
            v.x += a2.x; v.y += a2.y; v.z += a2.z; v.w += a2.w;
            const size_t ix = (size_t)m * 256 + (col >> 2);
            const float cc = sigf(v.y) * tcio[ix] + sigf(v.x) * tanhf(v.z);
            tcio[ix] = cc;
            thout[ix] = rnd32(sigf(v.w) * tanhf(cc));
        } else {
            *(float4*)(lstmin + (size_t)m * 1280 + col) = v;
        }
    }
    __syncthreads();
}

__device__ __forceinline__ void compose_part(
    const int tid, const int bx, const RedMeta& rm,
    const float* __restrict__ Wout, const float* __restrict__ bout,
    float* __restrict__ out1, const float* __restrict__ lstmin)
{
    const int w = tid >> 5, lane = tid & 31;
    const int b = bx * 8 + w;
    const float* L = lstmin + (size_t)b * 1280;
    float s0 = 0.f, s1 = 0.f, s2 = 0.f;
    #pragma unroll
    for (int i = 0; i < 8; i++) {
        const int t = lane + 32 * i;
        const float a  = tanhf(__ldcv(L + t));
        const float ig = sigf(__ldcv(L + 256 + t));
        const float f1 = sigf(__ldcv(L + 512 + t));
        const float f2 = sigf(__ldcv(L + 768 + t));
        const float og = sigf(__ldcv(L + 1024 + t));
        const float c = a * ig + f1 * rm.lc[(size_t)b * rm.lcs + t]
                              + f2 * rm.rc[(size_t)b * rm.rcs + t];
        const float h = og * tanhf(c);
        rm.Cr[b * 256 + t] = c;
        rm.Hr[b * 256 + t] = rnd32(h);
        s0 += h * Wout[t]; s1 += h * Wout[256 + t]; s2 += h * Wout[512 + t];
    }
    #pragma unroll
    for (int off = 16; off > 0; off >>= 1) {
        s0 += __shfl_down_sync(0xffffffffu, s0, off);
        s1 += __shfl_down_sync(0xffffffffu, s1, off);
        s2 += __shfl_down_sync(0xffffffffu, s2, off);
    }
    if (lane == 0) {
        const float l0 = s0 + bout[0], l1 = s1 + bout[1], l2 = s2 + bout[2];
        const float mx = fmaxf(l0, fmaxf(l1, l2));
        const float ls = mx + logf(expf(l0 - mx) + expf(l1 - mx) + expf(l2 - mx));
        out1[b * 3 + 0] = l0 - ls; out1[b * 3 + 1] = l1 - ls; out1[b * 3 + 2] = l2 - ls;
    }
}

__global__ __launch_bounds__(256, 1) void persist_k(
    float* __restrict__ out, const float* __restrict__ left_b,
    const float* __restrict__ Wout, const float* __restrict__ bout)
{
    extern __shared__ float dsm[];
    const int tid = threadIdx.x, bx = blockIdx.x;
    unsigned goal = G_;
    int cur = 0;
    const int mt = bx & 15, nt = bx >> 4;

    for (int t = 0; t < 127; t++) {
        const TrkMeta tm = g_tm[t];
        gemm_tile<0>(dsm, tid, mt, nt, tm.W, tm.seg0, tm.s0s,
                     g_th + (size_t)cur * B_ * 256, g_btrk,
                     tm.addA, 2048, tm.addB, tm.addBld,
                     g_tc, g_th + (size_t)(cur ^ 1) * B_ * 256, nullptr);
        grid_bar(goal);
        cur ^= 1;
        if (tm.isred) {
            const RedMeta rm = g_rm[t];
            for (int tl = bx; tl < 160; tl += G_)
                gemm_tile<1>(dsm, tid, tl & 15, tl >> 4, rm.W, rm.sg, rm.sgs,
                             g_th + (size_t)cur * B_ * 256, left_b,
                             rm.addA, 1280, nullptr, 0,
                             nullptr, nullptr, g_lstmin);
            grid_bar(goal);
            compose_part(tid, bx, rm, Wout, bout,
                         out + OUT0SZ + (size_t)rm.r * B_ * 3, g_lstmin);
            grid_bar(goal);
        }
    }
}

// ---------------- Metadata init (device-side stack simulation) ----------------
__global__ void init_meta_k() {
    if (threadIdx.x != 0 || blockIdx.x != 0) return;
    struct LSlot { bool red; int j; const float* h; long hs; const float* c; int cs; };
    LSlot slot[68];
    slot[0] = { false, 126, g_bufR + 126 * 256, 0, g_buf + 126 * 256, 0 };
    slot[1] = slot[0];
    int p = 2, k = 0, r = 0;
    for (int t = 0; t < 127; t++) {
        const bool isShift = (t < 2) || (t < 126 && (t % 2) == 0);
        const LSlot s1 = slot[p - 1], s2 = slot[p - 2];
        TrkMeta tm;
        if (s2.red) {
            tm.seg0 = s2.h; tm.s0s = s2.hs; tm.W = g_WtrkB;
            tm.addB = g_P12 + (size_t)s1.j * B_ * 2048 + 1024; tm.addBld = 2048;
        } else {
            tm.seg0 = s1.h; tm.s0s = s1.hs; tm.W = g_WtrkA;
            const int pj = (s2.j == 126) ? 2 : s2.j;
            tm.addB = g_P3 + (size_t)pj * B_ * 1024;
            tm.addBld = (s2.j == 126) ? 0 : 1024;
        }
        tm.addA = g_P12 + (size_t)k * B_ * 2048;
        tm.isred = isShift ? 0 : 1;
        g_tm[t] = tm;

        if (isShift) {
            LSlot ns; ns.red = false; ns.j = k;
            ns.h = g_bufR + (size_t)k * 256; ns.hs = (long)NTR_ * 256;
            ns.c = g_buf + (size_t)k * 256;  ns.cs = NTR_ * 256;
            slot[p] = ns; p++; k++;
        } else {
            const LSlot L = slot[p - 2], R = slot[p - 1];
            RedMeta rm;
            if (R.red) { rm.sg = R.h; rm.sgs = R.hs; rm.W = g_WredB; rm.addA = g_Plw; }
            else       { rm.sg = L.h; rm.sgs = L.hs; rm.W = g_WredA;
                         rm.addA = g_Prw + (size_t)(R.j - 2) * B_ * 1280; }
            rm.lc = L.c; rm.lcs = L.cs; rm.rc = R.c; rm.rcs = R.cs;
            rm.Hr = g_Hred + (size_t)r * B_ * 256;
            rm.Cr = g_Cred + (size_t)r * B_ * 256;
            rm.r = r;
            g_rm[t] = rm;
            LSlot ns; ns.red = true; ns.j = r;
            ns.h = rm.Hr; ns.hs = 256; ns.c = rm.Cr; ns.cs = 256;
            slot[p - 2] = ns; p--; r++;
        }
    }
}

// =====================================================================
// Parallel tf32 wmma GEMM (precompute): tile 64x64, 128 thr, 3-stage
// AMODE 1: row gather ; AMODE 2: buf-column view w/ scatter
// EPI 0: +bias+adds ; EPI 1: selu, dual write (full + rounded)
// =====================================================================
template<int AMODE, int EPI>
__global__ __launch_bounds__(128, 4) void tgemm(
    int nchunks, const float* __restrict__ Wt,
    float* __restrict__ C, int ldc,
    const float* __restrict__ bias,
    const float* __restrict__ addA, int lda,
    const float* __restrict__ addB, int ldb,
    const float* __restrict__ tcin, float* __restrict__ thout, float* __restrict__ tcout,
    const float* __restrict__ p0, long s0,
    const float* __restrict__ p1, long s1,
    const int* __restrict__ gidx, int ncols)
{
    extern __shared__ float dsm[];
    const int tid = threadIdx.x;
    float* stA[3]; float* stB[3];
    uint32_t uA[3], uB[3];
    #pragma unroll
    for (int s = 0; s < 3; s++) {
        stA[s] = dsm + s * 4608; stB[s] = stA[s] + 2304;
        uA[s] = smem_u32(stA[s]); uB[s] = smem_u32(stB[s]);
    }
    const int lrow = tid >> 1;
    const int lcol = (tid & 1) * 16;
    const long m_l = (long)blockIdx.y * 64 + lrow;
    const float* arow0 = nullptr;
    if (AMODE == 1) arow0 = p0 + (size_t)gidx[m_l] * 256;
    else {
        const long b = m_l / ncols, c = m_l - b * ncols;
        arow0 = p0 + ((size_t)b * 127 + gidx[c]) * 256;
    }
    auto loadA = [&](int ch, int st) {
        const float* src = arow0 + (ch << 5) + lcol;
        const uint32_t d = uA[st] + (uint32_t)(lrow * 36 + lcol) * 4;
        cp16(d, src); cp16(d + 16, src + 4); cp16(d + 32, src + 8); cp16(d + 48, src + 12);
    };
    auto loadB = [&](int ch, int st) {
        const float* src = Wt + ((size_t)blockIdx.x * nchunks + ch) * 2048 + lrow * 32 + lcol;
        const uint32_t d = uB[st] + (uint32_t)(lrow * 36 + lcol) * 4;
        cp16(d, src); cp16(d + 16, src + 4); cp16(d + 32, src + 8); cp16(d + 48, src + 12);
    };

    wmma::fragment<wmma::accumulator, 16, 16, 8, float> fc[2][2];
    #pragma unroll
    for (int i = 0; i < 2; i++)
        #pragma unroll
        for (int j = 0; j < 2; j++) wmma::fill_fragment(fc[i][j], 0.0f);

    loadA(0, 0); loadB(0, 0);
    asm volatile("cp.async.commit_group;" ::: "memory");
    loadA(1, 1); loadB(1, 1);
    asm volatile("cp.async.commit_group;" ::: "memory");

    const int wm = (tid >> 5) & 1;
    const int wn = tid >> 6;

    for (int c = 0; c < nchunks; c++) {
        if (c + 2 < nchunks) asm volatile("cp.async.wait_group 1;" ::: "memory");
        else                 asm volatile("cp.async.wait_group 0;" ::: "memory");
        __syncthreads();
        if (c + 2 < nchunks) {
            loadA(c + 2, (c + 2) % 3); loadB(c + 2, (c + 2) % 3);
            asm volatile("cp.async.commit_group;" ::: "memory");
        }
        const float* As_ = stA[c % 3];
        const float* Bs_ = stB[c % 3];
        #pragma unroll
        for (int ks = 0; ks < 4; ks++) {
            wmma::fragment<wmma::matrix_a, 16, 16, 8, wmma::precision::tf32, wmma::row_major> fa[2];
            wmma::fragment<wmma::matrix_b, 16, 16, 8, wmma::precision::tf32, wmma::col_major> fb[2];
            #pragma unroll
            for (int mi = 0; mi < 2; mi++)
                wmma::load_matrix_sync(fa[mi], As_ + (wm * 32 + mi * 16) * 36 + ks * 8, 36);
            #pragma unroll
            for (int nj = 0; nj < 2; nj++)
                wmma::load_matrix_sync(fb[nj], Bs_ + (wn * 32 + nj * 16) * 36 + ks * 8, 36);
            #pragma unroll
            for (int mi = 0; mi < 2; mi++)
                #pragma unroll
                for (int nj = 0; nj < 2; nj++)
                    wmma::mma_sync(fc[mi][nj], fa[mi], fb[nj], fc[mi][nj]);
        }
    }

    __syncthreads();
    float* Cs = dsm;
    #pragma unroll
    for (int mi = 0; mi < 2; mi++)
        #pragma unroll
        for (int nj = 0; nj < 2; nj++)
            wmma::store_matrix_sync(Cs + (wm * 32 + mi * 16) * 68 + wn * 32 + nj * 16,
                                    fc[mi][nj], 68, wmma::mem_row_major);
    __syncthreads();

    for (int idx = tid; idx < 1024; idx += 128) {
        const int row = idx >> 4, q = idx & 15;
        float4 v = *(const float4*)&Cs[row * 68 + q * 4];
        const int col = blockIdx.x * 64 + q * 4;
        const size_t m = (size_t)blockIdx.y * 64 + row;
        if (bias) {
            v.x += bias[col]; v.y += bias[col + 1]; v.z += bias[col + 2]; v.w += bias[col + 3];
        }
        size_t off;
        if (AMODE == 2) {
            const size_t b = m / ncols, c2 = m - b * ncols;
            off = (c2 * B_ + b) * (size_t)ldc + col;
        } else off = m * (size_t)ldc + col;
        if (EPI == 1) {
            v.x = (v.x > 0.f) ? 1.0507009873554805f * v.x : 1.7580993408473766f * expm1f(v.x);
            v.y = (v.y > 0.f) ? 1.0507009873554805f * v.y : 1.7580993408473766f * expm1f(v.y);
            v.z = (v.z > 0.f) ? 1.0507009873554805f * v.z : 1.7580993408473766f * expm1f(v.z);
            v.w = (v.w > 0.f) ? 1.0507009873554805f * v.w : 1.7580993408473766f * expm1f(v.w);
            *(float4*)(C + off) = v;
            float4 vr; vr.x = rnd32(v.x); vr.y = rnd32(v.y); vr.z = rnd32(v.z); vr.w = rnd32(v.w);
            *(float4*)(thout + off) = vr;
        } else {
            *(float4*)(C + off) = v;
        }
    }
}

// ---------------- Weight packing ----------------
__device__ __forceinline__ void putT(float* dst, int nck, int n, int k, float v) {
    dst[(((size_t)(n >> 6) * nck + (k >> 5)) << 11) + ((n & 63) << 5) + (k & 31)] = rnd32(v);
}

__global__ void pack_k(const float* __restrict__ w_ih, const float* __restrict__ w_hh,
                       const float* __restrict__ b_ih, const float* __restrict__ b_hh,
                       const float* __restrict__ lw, const float* __restrict__ rw,
                       const float* __restrict__ tw, const float* __restrict__ win)
{
    const int idx = blockIdx.x * blockDim.x + threadIdx.x;
    if (idx < 2048 * 256) {
        const int np = idx >> 8, k = idx & 255;
        const int half = np >> 10, q = np & 1023;
        const int n = (q & 3) * 256 + (q >> 2);
        putT(g_Wc12, 8, np, k, half ? w_ih[n * 768 + 256 + k] : w_ih[n * 768 + k]);
    }
    if (idx < 1024 * 256) {
        const int np = idx >> 8, k = idx & 255;
        const int n = (np & 3) * 256 + (np >> 2);
        putT(g_W3i, 8, np, k, w_ih[n * 768 + 512 + k]);
    }
    if (idx < 1024 * 512) {
        const int np = idx >> 9, k = idx & 511;
        const int n = (np & 3) * 256 + (np >> 2);
        putT(g_WtrkA, 16, np, k, (k < 256) ? w_ih[n * 768 + 256 + k] : w_hh[n * 256 + (k - 256)]);
        putT(g_WtrkB, 16, np, k, (k < 256) ? w_ih[n * 768 + 512 + k] : w_hh[n * 256 + (k - 256)]);
    }
    if (idx < 1280 * 512) {
        const int n = idx >> 9, k = idx & 511;
        putT(g_WredA, 16, n, k, (k < 256) ? lw[n * 256 + k] : tw[n * 256 + k - 256]);
        putT(g_WredB, 16, n, k, (k < 256) ? rw[n * 256 + k] : tw[n * 256 + k - 256]);
    }
    if (idx < 1280 * 256) {
        const int n = idx >> 8, k = idx & 255;
        putT(g_Rw, 8, n, k, rw[n * 256 + k]);
        putT(g_Lw, 8, n, k, lw[n * 256 + k]);
    }
    if (idx < 256 * 256) putT(g_Win, 8, idx >> 8, idx & 255, win[idx]);
    if (idx < 1024) {
        const int n = (idx & 3) * 256 + (idx >> 2);
        g_btrk[idx] = b_ih[n] + b_hh[n];
    }
    if (idx < 2 * B_ * 256) {
        g_th[idx] = 0.0f;
        if (idx < B_ * 256) g_tc[idx] = 0.0f;
    }
    if (idx < 132)
        g_cmap[idx] = (idx < 66) ? ((idx == 65) ? 126 : idx)
                    : (idx < 69) ? ((idx == 68) ? 126 : idx - 66)
                    : (idx < 131) ? (idx - 69 + 2) : 0;
}

__global__ void round_embed_k(const float* __restrict__ e) {
    const size_t idx = (size_t)blockIdx.x * blockDim.x + threadIdx.x;
    if (idx < (size_t)50000 * 256) g_embedR[idx] = rnd32(e[idx]);
}

// ---------------- outputs0 ----------------
__global__ void out0_k(const float* __restrict__ buf,
                       const float* __restrict__ Wout, const float* __restrict__ bout,
                       float* __restrict__ out0)
{
    const int gw = (blockIdx.x * blockDim.x + threadIdx.x) >> 5;
    const int lane = threadIdx.x & 31;
    if (gw >= B_ * NTR_) return;
    const float* x = buf + (size_t)gw * 256;
    float s0 = 0.f, s1 = 0.f, s2 = 0.f;
    #pragma unroll
    for (int t = lane; t < 256; t += 32) {
        const float v = x[t];
        s0 += v * Wout[t]; s1 += v * Wout[256 + t]; s2 += v * Wout[512 + t];
    }
    #pragma unroll
    for (int off = 16; off > 0; off >>= 1) {
        s0 += __shfl_down_sync(0xffffffffu, s0, off);
        s1 += __shfl_down_sync(0xffffffffu, s1, off);
        s2 += __shfl_down_sync(0xffffffffu, s2, off);
    }
    if (lane == 0) {
        const int b = gw / NTR_, n = gw % NTR_;
        const float l0 = s0 + bout[0], l1 = s1 + bout[1], l2 = s2 + bout[2];
        const float mx = fmaxf(l0, fmaxf(l1, l2));
        const float ls = mx + logf(expf(l0 - mx) + expf(l1 - mx) + expf(l2 - mx));
        float* o = out0 + ((size_t)n * B_ + b) * 3;
        o[0] = l0 - ls; o[1] = l1 - ls; o[2] = l2 - ls;
    }
}

// ---------------- Host driver ----------------
extern "C" void kernel_launch(void* const* d_in, const int* in_sizes, int n_in,
                              void* d_out, int out_size)
{
    const int*   tokens  = (const int*)d_in[0];
    const float* embed   = (const float*)d_in[2];
    const float* W_in_w  = (const float*)d_in[3];
    const float* W_in_b  = (const float*)d_in[4];
    const float* left_w  = (const float*)d_in[5];
    const float* left_b  = (const float*)d_in[6];
    const float* right_w = (const float*)d_in[7];
    const float* track_w = (const float*)d_in[8];
    const float* w_ih    = (const float*)d_in[9];
    const float* w_hh    = (const float*)d_in[10];
    const float* b_ih    = (const float*)d_in[11];
    const float* b_hh    = (const float*)d_in[12];
    const float* Wout    = (const float*)d_in[13];
    const float* bout    = (const float*)d_in[14];
    float* out = (float*)d_out;
    (void)in_sizes; (void)n_in; (void)out_size;

    float *buf, *bufR, *embedR, *P12, *P3, *Prw, *Plw;
    float *Wc12, *W3i, *Rw, *Lw, *Win;
    int* cmap;
    cudaGetSymbolAddress((void**)&buf,    g_buf);
    cudaGetSymbolAddress((void**)&bufR,   g_bufR);
    cudaGetSymbolAddress((void**)&embedR, g_embedR);
    cudaGetSymbolAddress((void**)&P12,    g_P12);
    cudaGetSymbolAddress((void**)&P3,     g_P3);
    cudaGetSymbolAddress((void**)&Prw,    g_Prw);
    cudaGetSymbolAddress((void**)&Plw,    g_Plw);
    cudaGetSymbolAddress((void**)&Wc12,   g_Wc12);
    cudaGetSymbolAddress((void**)&W3i,    g_W3i);
    cudaGetSymbolAddress((void**)&Rw,     g_Rw);
    cudaGetSymbolAddress((void**)&Lw,     g_Lw);
    cudaGetSymbolAddress((void**)&Win,    g_Win);
    cudaGetSymbolAddress((void**)&cmap,   g_cmap);

    cudaFuncSetAttribute((const void*)tgemm<1, 1>, cudaFuncAttributeMaxDynamicSharedMemorySize, SMEMB);
    cudaFuncSetAttribute((const void*)tgemm<2, 0>, cudaFuncAttributeMaxDynamicSharedMemorySize, SMEMB);
    cudaFuncSetAttribute((const void*)persist_k,   cudaFuncAttributeMaxDynamicSharedMemorySize, SMEMB);

    // 1) pack + round + metadata
    pack_k<<<2560, 256>>>(w_ih, w_hh, b_ih, b_hh, left_w, right_w, track_w, W_in_w);
    round_embed_k<<<50000, 256>>>(embed);
    init_meta_k<<<1, 1>>>();
    reset_bar_k<<<1, 1>>>();

    // 2) buf = selu(embed[tokens] @ Win^T + b); dual write full + rounded
    tgemm<1, 1><<<dim3(4, 2032), 128, SMEMB>>>(
        8, Win, buf, 256, W_in_b, nullptr, 0, nullptr, 0,
        nullptr, bufR, nullptr,
        embedR, 0, nullptr, 0, tokens, 0);

    // 3) outputs0
    out0_k<<<(B_ * NTR_ * 32) / 256, 256>>>(buf, Wout, bout, out);

    // 4) parallel precomputes
    tgemm<2, 0><<<dim3(32, 1056), 128, SMEMB>>>(
        8, Wc12, P12, 2048, nullptr, nullptr, 0, nullptr, 0,
        nullptr, nullptr, nullptr, bufR, 0, nullptr, 0, cmap, 66);
    tgemm<2, 0><<<dim3(16, 48), 128, SMEMB>>>(
        8, W3i, P3, 1024, nullptr, nullptr, 0, nullptr, 0,
        nullptr, nullptr, nullptr, bufR, 0, nullptr, 0, cmap + 66, 3);
    tgemm<2, 0><<<dim3(20, 992), 128, SMEMB>>>(
        8, Rw, Prw, 1280, nullptr, nullptr, 0, nullptr, 0,
        nullptr, nullptr, nullptr, bufR, 0, nullptr, 0, cmap + 69, 62);
    tgemm<2, 0><<<dim3(20, 16), 128, SMEMB>>>(
        8, Lw, Plw, 1280, nullptr, nullptr, 0, nullptr, 0,
        nullptr, nullptr, nullptr, bufR, 0, nullptr, 0, cmap + 131, 1);

    // 5) entire sequential chain in ONE persistent kernel
    persist_k<<<G_, 256, SMEMB>>>(out, left_b, Wout, bout);
}

// round 17
// speedup vs baseline: 1.0063x; 1.0063x over previous
#include <cuda_runtime.h>
#include <mma.h>
#include <math.h>
#include <stdint.h>

using namespace nvcuda;

#define B_    1024
#define NTR_  127
#define NRED  63
#define OUT0SZ (NTR_ * B_ * 3)
#define SMEMB 55296   // parallel tgemm: 3 stages x (64x36 + 64x36) x4B ; persist: 2 x 6912 floats
#define G_    128     // persistent grid size

// ---------------- Device scratch ----------------
__device__ float g_buf [(size_t)B_ * NTR_ * 256];   // full precision
__device__ float g_bufR[(size_t)B_ * NTR_ * 256];   // tf32-rounded
__device__ float g_embedR[(size_t)50000 * 256];
__device__ float g_P12[(size_t)66 * B_ * 2048];
__device__ float g_P3 [(size_t)3 * B_ * 1024];
__device__ float g_Prw[(size_t)62 * B_ * 1280];
__device__ float g_Plw[(size_t)B_ * 1280];
__device__ float g_Hred[(size_t)NRED * B_ * 256];
__device__ float g_Cred[(size_t)NRED * B_ * 256];
__device__ float g_th[2 * B_ * 256];
__device__ float g_tc[B_ * 256];
__device__ float g_lstmin[(size_t)B_ * 1280];
__device__ float g_Wc12 [2048 * 256];
__device__ float g_W3i  [1024 * 256];
__device__ float g_WtrkA[1024 * 512];
__device__ float g_WtrkB[1024 * 512];
__device__ float g_WredA[1280 * 512];
__device__ float g_WredB[1280 * 512];
__device__ float g_Rw   [1280 * 256];
__device__ float g_Lw   [1280 * 256];
__device__ float g_Win  [256 * 256];
__device__ float g_btrk [1024];
__device__ int   g_cmap [132];

// persistent-kernel metadata + barrier
struct TrkMeta { const float* seg0; long s0s; const float* W;
                 const float* addA; const float* addB; int addBld; int isred; };
struct RedMeta { const float* sg; long sgs; const float* W; const float* addA;
                 const float* lc; int lcs; const float* rc; int rcs;
                 float* Hr; float* Cr; int r; };
__device__ TrkMeta g_tm[127];
__device__ RedMeta g_rm[127];
__device__ unsigned g_barc;

__device__ __forceinline__ uint32_t smem_u32(const void* p) {
    uint32_t a;
    asm("{ .reg .u64 t; cvta.to.shared.u64 t, %1; cvt.u32.u64 %0, t; }" : "=r"(a) : "l"(p));
    return a;
}
__device__ __forceinline__ float sigf(float x) { return 1.0f / (1.0f + expf(-x)); }
__device__ __forceinline__ float rnd32(float x) {
    float y; asm("cvt.rna.tf32.f32 %0,%1;" : "=f"(y) : "f"(x)); return y;
}
__device__ __forceinline__ void cp16(uint32_t d, const float* s) {
    asm volatile("cp.async.cg.shared.global [%0], [%1], 16;" :: "r"(d), "l"(s) : "memory");
}

__device__ __forceinline__ void grid_bar(unsigned& goal) {
    __syncthreads();
    if (threadIdx.x == 0) {
        __threadfence();
        atomicAdd(&g_barc, 1u);
        while (*(volatile unsigned*)&g_barc < goal) __nanosleep(32);
        __threadfence();
    }
    __syncthreads();
    goal += G_;
}

__global__ void reset_bar_k() { g_barc = 0u; }

// =====================================================================
// Persistent-kernel GEMM tile: 64(M) x 128(N), K=512 (seg0 256 | th 256),
// 256 threads, 2-stage cp.async.cg double buffer.
// MODE 0: tracker — fused interleaved-gate LSTM cell epilogue
// MODE 1: reduce  — lstmin = acc + bias + addA
// =====================================================================
template<int MODE>
__device__ __forceinline__ void gemm_tile(
    float* dsm, const int tid, const int mt, const int nt,
    const float* __restrict__ W,
    const float* __restrict__ seg0, const long s0s,
    const float* __restrict__ th,
    const float* __restrict__ bias,
    const float* __restrict__ addA, const int adAld,
    const float* __restrict__ addB, const int adBld,
    float* __restrict__ tcio, float* __restrict__ thout,
    float* __restrict__ lstmin)
{
    const uint32_t uS = smem_u32(dsm);
    const int r4 = tid >> 2, c8 = (tid & 3) << 3;
    const int rB = tid >> 1, cB = (tid & 1) << 4;
    const long mA = (long)mt * 64 + r4;
    const float* segrow = seg0 + mA * s0s + c8;
    const float* throw_ = th + mA * 256 + c8;
    const float* wrow = W + ((size_t)nt * 2 + (tid >> 7)) * 16 * 2048
                          + (size_t)(rB & 63) * 32 + cB;

    auto ldst = [&](int ch, int st) {
        const uint32_t base = uS + (uint32_t)st * (6912u * 4u);
        const float* sa = (ch < 8) ? (segrow + ch * 32) : (throw_ + (ch - 8) * 32);
        const uint32_t dA = base + (uint32_t)(r4 * 36 + c8) * 4;
        cp16(dA, sa); cp16(dA + 16, sa + 4);
        const float* sb = wrow + (size_t)ch * 2048;
        const uint32_t dB = base + 9216u + (uint32_t)(rB * 36 + cB) * 4;
        cp16(dB, sb); cp16(dB + 16, sb + 4); cp16(dB + 32, sb + 8); cp16(dB + 48, sb + 12);
        asm volatile("cp.async.commit_group;" ::: "memory");
    };

    wmma::fragment<wmma::accumulator, 16, 16, 8, float> fc[2][2];
    #pragma unroll
    for (int i = 0; i < 2; i++)
        #pragma unroll
        for (int j = 0; j < 2; j++) wmma::fill_fragment(fc[i][j], 0.0f);

    const int wid = tid >> 5, wm = wid & 1, wn = wid >> 1;

    ldst(0, 0);
    for (int ch = 0; ch < 16; ch++) {
        if (ch + 1 < 16) {
            ldst(ch + 1, (ch + 1) & 1);
            asm volatile("cp.async.wait_group 1;" ::: "memory");
        } else {
            asm volatile("cp.async.wait_group 0;" ::: "memory");
        }
        __syncthreads();
        const float* As = dsm + (ch & 1) * 6912;
        const float* Bs = As + 2304;
        #pragma unroll
        for (int ks = 0; ks < 4; ks++) {
            wmma::fragment<wmma::matrix_a, 16, 16, 8, wmma::precision::tf32, wmma::row_major> fa[2];
            wmma::fragment<wmma::matrix_b, 16, 16, 8, wmma::precision::tf32, wmma::col_major> fb[2];
            #pragma unroll
            for (int mi = 0; mi < 2; mi++)
                wmma::load_matrix_sync(fa[mi], As + (wm * 32 + mi * 16) * 36 + ks * 8, 36);
            #pragma unroll
            for (int nj = 0; nj < 2; nj++)
                wmma::load_matrix_sync(fb[nj], Bs + (wn * 32 + nj * 16) * 36 + ks * 8, 36);
            #pragma unroll
            for (int mi = 0; mi < 2; mi++)
                #pragma unroll
                for (int nj = 0; nj < 2; nj++)
                    wmma::mma_sync(fc[mi][nj], fa[mi], fb[nj], fc[mi][nj]);
        }
        __syncthreads();
    }

    float* Cs = dsm;   // 64 x 132 staging
    #pragma unroll
    for (int mi = 0; mi < 2; mi++)
        #pragma unroll
        for (int nj = 0; nj < 2; nj++)
            wmma::store_matrix_sync(Cs + (wm * 32 + mi * 16) * 132 + wn * 32 + nj * 16,
                                    fc[mi][nj], 132, wmma::mem_row_major);
    __syncthreads();

    for (int idx = tid; idx < 2048; idx += 256) {
        const int row = idx >> 5, q = idx & 31;
        float4 v = *(const float4*)&Cs[row * 132 + q * 4];
        const int col = nt * 128 + q * 4;
        const long m = (long)mt * 64 + row;
        v.x += bias[col]; v.y += bias[col + 1]; v.z += bias[col + 2]; v.w += bias[col + 3];
        {
            const float4 a = *(const float4*)(addA + (size_t)m * adAld + col);
            v.x += a.x; v.y += a.y; v.z += a.z; v.w += a.w;
        }
        if (MODE == 0) {
            const float4 a2 = *(const float4*)(addB + (size_t)m * adBld + col);
            v.x += a2.x; v.y += a2.y; v.z += a2.z; v.w += a2.w;
            const size_t ix = (size_t)m * 256 + (col >> 2);
            const float cc = sigf(v.y) * tcio[ix] + sigf(v.x) * tanhf(v.z);
            tcio[ix] = cc;
            thout[ix] = rnd32(sigf(v.w) * tanhf(cc));
        } else {
            *(float4*)(lstmin + (size_t)m * 1280 + col) = v;
        }
    }
    __syncthreads();
}

__device__ __forceinline__ void compose_part(
    const int tid, const int bx, const RedMeta& rm,
    const float* __restrict__ Wout, const float* __restrict__ bout,
    float* __restrict__ out1, const float* __restrict__ lstmin)
{
    const int w = tid >> 5, lane = tid & 31;
    const int b = bx * 8 + w;
    const float* L = lstmin + (size_t)b * 1280;
    float s0 = 0.f, s1 = 0.f, s2 = 0.f;
    #pragma unroll
    for (int i = 0; i < 8; i++) {
        const int t = lane + 32 * i;
        const float a  = tanhf(__ldcv(L + t));
        const float ig = sigf(__ldcv(L + 256 + t));
        const float f1 = sigf(__ldcv(L + 512 + t));
        const float f2 = sigf(__ldcv(L + 768 + t));
        const float og = sigf(__ldcv(L + 1024 + t));
        const float c = a * ig + f1 * rm.lc[(size_t)b * rm.lcs + t]
                              + f2 * rm.rc[(size_t)b * rm.rcs + t];
        const float h = og * tanhf(c);
        rm.Cr[b * 256 + t] = c;
        rm.Hr[b * 256 + t] = rnd32(h);
        s0 += h * Wout[t]; s1 += h * Wout[256 + t]; s2 += h * Wout[512 + t];
    }
    #pragma unroll
    for (int off = 16; off > 0; off >>= 1) {
        s0 += __shfl_down_sync(0xffffffffu, s0, off);
        s1 += __shfl_down_sync(0xffffffffu, s1, off);
        s2 += __shfl_down_sync(0xffffffffu, s2, off);
    }
    if (lane == 0) {
        const float l0 = s0 + bout[0], l1 = s1 + bout[1], l2 = s2 + bout[2];
        const float mx = fmaxf(l0, fmaxf(l1, l2));
        const float ls = mx + logf(expf(l0 - mx) + expf(l1 - mx) + expf(l2 - mx));
        out1[b * 3 + 0] = l0 - ls; out1[b * 3 + 1] = l1 - ls; out1[b * 3 + 2] = l2 - ls;
    }
}

__global__ __launch_bounds__(256, 1) void persist_k(
    float* __restrict__ out, const float* __restrict__ left_b,
    const float* __restrict__ Wout, const float* __restrict__ bout)
{
    extern __shared__ float dsm[];
    const int tid = threadIdx.x, bx = blockIdx.x;
    unsigned goal = G_;
    int cur = 0;
    const int mt = bx & 15, nt = bx >> 4;

    for (int t = 0; t < 127; t++) {
        const TrkMeta tm = g_tm[t];
        gemm_tile<0>(dsm, tid, mt, nt, tm.W, tm.seg0, tm.s0s,
                     g_th + (size_t)cur * B_ * 256, g_btrk,
                     tm.addA, 2048, tm.addB, tm.addBld,
                     g_tc, g_th + (size_t)(cur ^ 1) * B_ * 256, nullptr);
        grid_bar(goal);
        cur ^= 1;
        if (tm.isred) {
            const RedMeta rm = g_rm[t];
            for (int tl = bx; tl < 160; tl += G_)
                gemm_tile<1>(dsm, tid, tl & 15, tl >> 4, rm.W, rm.sg, rm.sgs,
                             g_th + (size_t)cur * B_ * 256, left_b,
                             rm.addA, 1280, nullptr, 0,
                             nullptr, nullptr, g_lstmin);
            grid_bar(goal);
            compose_part(tid, bx, rm, Wout, bout,
                         out + OUT0SZ + (size_t)rm.r * B_ * 3, g_lstmin);
            grid_bar(goal);
        }
    }
}

// ---------------- Metadata init (device-side stack simulation) ----------------
__global__ void init_meta_k() {
    if (threadIdx.x != 0 || blockIdx.x != 0) return;
    struct LSlot { bool red; int j; const float* h; long hs; const float* c; int cs; };
    LSlot slot[68];
    slot[0] = { false, 126, g_bufR + 126 * 256, 0, g_buf + 126 * 256, 0 };
    slot[1] = slot[0];
    int p = 2, k = 0, r = 0;
    for (int t = 0; t < 127; t++) {
        const bool isShift = (t < 2) || (t < 126 && (t % 2) == 0);
        const LSlot s1 = slot[p - 1], s2 = slot[p - 2];
        TrkMeta tm;
        if (s2.red) {
            tm.seg0 = s2.h; tm.s0s = s2.hs; tm.W = g_WtrkB;
            tm.addB = g_P12 + (size_t)s1.j * B_ * 2048 + 1024; tm.addBld = 2048;
        } else {
            tm.seg0 = s1.h; tm.s0s = s1.hs; tm.W = g_WtrkA;
            const int pj = (s2.j == 126) ? 2 : s2.j;
            tm.addB = g_P3 + (size_t)pj * B_ * 1024;
            tm.addBld = (s2.j == 126) ? 0 : 1024;
        }
        tm.addA = g_P12 + (size_t)k * B_ * 2048;
        tm.isred = isShift ? 0 : 1;
        g_tm[t] = tm;

        if (isShift) {
            LSlot ns; ns.red = false; ns.j = k;
            ns.h = g_bufR + (size_t)k * 256; ns.hs = (long)NTR_ * 256;
            ns.c = g_buf + (size_t)k * 256;  ns.cs = NTR_ * 256;
            slot[p] = ns; p++; k++;
        } else {
            const LSlot L = slot[p - 2], R = slot[p - 1];
            RedMeta rm;
            if (R.red) { rm.sg = R.h; rm.sgs = R.hs; rm.W = g_WredB; rm.addA = g_Plw; }
            else       { rm.sg = L.h; rm.sgs = L.hs; rm.W = g_WredA;
                         rm.addA = g_Prw + (size_t)(R.j - 2) * B_ * 1280; }
            rm.lc = L.c; rm.lcs = L.cs; rm.rc = R.c; rm.rcs = R.cs;
            rm.Hr = g_Hred + (size_t)r * B_ * 256;
            rm.Cr = g_Cred + (size_t)r * B_ * 256;
            rm.r = r;
            g_rm[t] = rm;
            LSlot ns; ns.red = true; ns.j = r;
            ns.h = rm.Hr; ns.hs = 256; ns.c = rm.Cr; ns.cs = 256;
            slot[p - 2] = ns; p--; r++;
        }
    }
}

// =====================================================================
// Parallel tf32 wmma GEMM (precompute): tile 64x64, 128 thr, 3-stage
// AMODE 1: row gather ; AMODE 2: buf-column view w/ scatter
// EPI 0: +bias+adds ; EPI 1: selu, dual write (full + rounded)
// =====================================================================
template<int AMODE, int EPI>
__global__ __launch_bounds__(128, 4) void tgemm(
    int nchunks, const float* __restrict__ Wt,
    float* __restrict__ C, int ldc,
    const float* __restrict__ bias,
    const float* __restrict__ addA, int lda,
    const float* __restrict__ addB, int ldb,
    const float* __restrict__ tcin, float* __restrict__ thout, float* __restrict__ tcout,
    const float* __restrict__ p0, long s0,
    const float* __restrict__ p1, long s1,
    const int* __restrict__ gidx, int ncols)
{
    extern __shared__ float dsm[];
    const int tid = threadIdx.x;
    float* stA[3]; float* stB[3];
    uint32_t uA[3], uB[3];
    #pragma unroll
    for (int s = 0; s < 3; s++) {
        stA[s] = dsm + s * 4608; stB[s] = stA[s] + 2304;
        uA[s] = smem_u32(stA[s]); uB[s] = smem_u32(stB[s]);
    }
    const int lrow = tid >> 1;
    const int lcol = (tid & 1) * 16;
    const long m_l = (long)blockIdx.y * 64 + lrow;
    const float* arow0 = nullptr;
    if (AMODE == 1) arow0 = p0 + (size_t)gidx[m_l] * 256;
    else {
        const long b = m_l / ncols, c = m_l - b * ncols;
        arow0 = p0 + ((size_t)b * 127 + gidx[c]) * 256;
    }
    auto loadA = [&](int ch, int st) {
        const float* src = arow0 + (ch << 5) + lcol;
        const uint32_t d = uA[st] + (uint32_t)(lrow * 36 + lcol) * 4;
        cp16(d, src); cp16(d + 16, src + 4); cp16(d + 32, src + 8); cp16(d + 48, src + 12);
    };
    auto loadB = [&](int ch, int st) {
        const float* src = Wt + ((size_t)blockIdx.x * nchunks + ch) * 2048 + lrow * 32 + lcol;
        const uint32_t d = uB[st] + (uint32_t)(lrow * 36 + lcol) * 4;
        cp16(d, src); cp16(d + 16, src + 4); cp16(d + 32, src + 8); cp16(d + 48, src + 12);
    };

    wmma::fragment<wmma::accumulator, 16, 16, 8, float> fc[2][2];
    #pragma unroll
    for (int i = 0; i < 2; i++)
        #pragma unroll
        for (int j = 0; j < 2; j++) wmma::fill_fragment(fc[i][j], 0.0f);

    loadA(0, 0); loadB(0, 0);
    asm volatile("cp.async.commit_group;" ::: "memory");
    loadA(1, 1); loadB(1, 1);
    asm volatile("cp.async.commit_group;" ::: "memory");

    const int wm = (tid >> 5) & 1;
    const int wn = tid >> 6;

    for (int c = 0; c < nchunks; c++) {
        if (c + 2 < nchunks) asm volatile("cp.async.wait_group 1;" ::: "memory");
        else                 asm volatile("cp.async.wait_group 0;" ::: "memory");
        __syncthreads();
        if (c + 2 < nchunks) {
            loadA(c + 2, (c + 2) % 3); loadB(c + 2, (c + 2) % 3);
            asm volatile("cp.async.commit_group;" ::: "memory");
        }
        const float* As_ = stA[c % 3];
        const float* Bs_ = stB[c % 3];
        #pragma unroll
        for (int ks = 0; ks < 4; ks++) {
            wmma::fragment<wmma::matrix_a, 16, 16, 8, wmma::precision::tf32, wmma::row_major> fa[2];
            wmma::fragment<wmma::matrix_b, 16, 16, 8, wmma::precision::tf32, wmma::col_major> fb[2];
            #pragma unroll
            for (int mi = 0; mi < 2; mi++)
                wmma::load_matrix_sync(fa[mi], As_ + (wm * 32 + mi * 16) * 36 + ks * 8, 36);
            #pragma unroll
            for (int nj = 0; nj < 2; nj++)
                wmma::load_matrix_sync(fb[nj], Bs_ + (wn * 32 + nj * 16) * 36 + ks * 8, 36);
            #pragma unroll
            for (int mi = 0; mi < 2; mi++)
                #pragma unroll
                for (int nj = 0; nj < 2; nj++)
                    wmma::mma_sync(fc[mi][nj], fa[mi], fb[nj], fc[mi][nj]);
        }
    }

    __syncthreads();
    float* Cs = dsm;
    #pragma unroll
    for (int mi = 0; mi < 2; mi++)
        #pragma unroll
        for (int nj = 0; nj < 2; nj++)
            wmma::store_matrix_sync(Cs + (wm * 32 + mi * 16) * 68 + wn * 32 + nj * 16,
                                    fc[mi][nj], 68, wmma::mem_row_major);
    __syncthreads();

    for (int idx = tid; idx < 1024; idx += 128) {
        const int row = idx >> 4, q = idx & 15;
        float4 v = *(const float4*)&Cs[row * 68 + q * 4];
        const int col = blockIdx.x * 64 + q * 4;
        const size_t m = (size_t)blockIdx.y * 64 + row;
        if (bias) {
            v.x += bias[col]; v.y += bias[col + 1]; v.z += bias[col + 2]; v.w += bias[col + 3];
        }
        size_t off;
        if (AMODE == 2) {
            const size_t b = m / ncols, c2 = m - b * ncols;
            off = (c2 * B_ + b) * (size_t)ldc + col;
        } else off = m * (size_t)ldc + col;
        if (EPI == 1) {
            v.x = (v.x > 0.f) ? 1.0507009873554805f * v.x : 1.7580993408473766f * expm1f(v.x);
            v.y = (v.y > 0.f) ? 1.0507009873554805f * v.y : 1.7580993408473766f * expm1f(v.y);
            v.z = (v.z > 0.f) ? 1.0507009873554805f * v.z : 1.7580993408473766f * expm1f(v.z);
            v.w = (v.w > 0.f) ? 1.0507009873554805f * v.w : 1.7580993408473766f * expm1f(v.w);
            *(float4*)(C + off) = v;
            float4 vr; vr.x = rnd32(v.x); vr.y = rnd32(v.y); vr.z = rnd32(v.z); vr.w = rnd32(v.w);
            *(float4*)(thout + off) = vr;
        } else {
            *(float4*)(C + off) = v;
        }
    }
}

// ---------------- Weight packing ----------------
__device__ __forceinline__ void putT(float* dst, int nck, int n, int k, float v) {
    dst[(((size_t)(n >> 6) * nck + (k >> 5)) << 11) + ((n & 63) << 5) + (k & 31)] = rnd32(v);
}

__global__ void pack_k(const float* __restrict__ w_ih, const float* __restrict__ w_hh,
                       const float* __restrict__ b_ih, const float* __restrict__ b_hh,
                       const float* __restrict__ lw, const float* __restrict__ rw,
                       const float* __restrict__ tw, const float* __restrict__ win)
{
    const int idx = blockIdx.x * blockDim.x + threadIdx.x;
    if (idx < 2048 * 256) {
        const int np = idx >> 8, k = idx & 255;
        const int half = np >> 10, q = np & 1023;
        const int n = (q & 3) * 256 + (q >> 2);
        putT(g_Wc12, 8, np, k, half ? w_ih[n * 768 + 256 + k] : w_ih[n * 768 + k]);
    }
    if (idx < 1024 * 256) {
        const int np = idx >> 8, k = idx & 255;
        const int n = (np & 3) * 256 + (np >> 2);
        putT(g_W3i, 8, np, k, w_ih[n * 768 + 512 + k]);
    }
    if (idx < 1024 * 512) {
        const int np = idx >> 9, k = idx & 511;
        const int n = (np & 3) * 256 + (np >> 2);
        putT(g_WtrkA, 16, np, k, (k < 256) ? w_ih[n * 768 + 256 + k] : w_hh[n * 256 + (k - 256)]);
        putT(g_WtrkB, 16, np, k, (k < 256) ? w_ih[n * 768 + 512 + k] : w_hh[n * 256 + (k - 256)]);
    }
    if (idx < 1280 * 512) {
        const int n = idx >> 9, k = idx & 511;
        putT(g_WredA, 16, n, k, (k < 256) ? lw[n * 256 + k] : tw[n * 256 + k - 256]);
        putT(g_WredB, 16, n, k, (k < 256) ? rw[n * 256 + k] : tw[n * 256 + k - 256]);
    }
    if (idx < 1280 * 256) {
        const int n = idx >> 8, k = idx & 255;
        putT(g_Rw, 8, n, k, rw[n * 256 + k]);
        putT(g_Lw, 8, n, k, lw[n * 256 + k]);
    }
    if (idx < 256 * 256) putT(g_Win, 8, idx >> 8, idx & 255, win[idx]);
    if (idx < 1024) {
        const int n = (idx & 3) * 256 + (idx >> 2);
        g_btrk[idx] = b_ih[n] + b_hh[n];
    }
    if (idx < 2 * B_ * 256) {
        g_th[idx] = 0.0f;
        if (idx < B_ * 256) g_tc[idx] = 0.0f;
    }
    if (idx < 132)
        g_cmap[idx] = (idx < 66) ? ((idx == 65) ? 126 : idx)
                    : (idx < 69) ? ((idx == 68) ? 126 : idx - 66)
                    : (idx < 131) ? (idx - 69 + 2) : 0;
}

__global__ void round_embed_k(const float* __restrict__ e) {
    const size_t idx = (size_t)blockIdx.x * blockDim.x + threadIdx.x;
    if (idx < (size_t)50000 * 256) g_embedR[idx] = rnd32(e[idx]);
}

// ---------------- outputs0 ----------------
__global__ void out0_k(const float* __restrict__ buf,
                       const float* __restrict__ Wout, const float* __restrict__ bout,
                       float* __restrict__ out0)
{
    const int gw = (blockIdx.x * blockDim.x + threadIdx.x) >> 5;
    const int lane = threadIdx.x & 31;
    if (gw >= B_ * NTR_) return;
    const float* x = buf + (size_t)gw * 256;
    float s0 = 0.f, s1 = 0.f, s2 = 0.f;
    #pragma unroll
    for (int t = lane; t < 256; t += 32) {
        const float v = x[t];
        s0 += v * Wout[t]; s1 += v * Wout[256 + t]; s2 += v * Wout[512 + t];
    }
    #pragma unroll
    for (int off = 16; off > 0; off >>= 1) {
        s0 += __shfl_down_sync(0xffffffffu, s0, off);
        s1 += __shfl_down_sync(0xffffffffu, s1, off);
        s2 += __shfl_down_sync(0xffffffffu, s2, off);
    }
    if (lane == 0) {
        const int b = gw / NTR_, n = gw % NTR_;
        const float l0 = s0 + bout[0], l1 = s1 + bout[1], l2 = s2 + bout[2];
        const float mx = fmaxf(l0, fmaxf(l1, l2));
        const float ls = mx + logf(expf(l0 - mx) + expf(l1 - mx) + expf(l2 - mx));
        float* o = out0 + ((size_t)n * B_ + b) * 3;
        o[0] = l0 - ls; o[1] = l1 - ls; o[2] = l2 - ls;
    }
}

// ---------------- Host driver ----------------
extern "C" void kernel_launch(void* const* d_in, const int* in_sizes, int n_in,
                              void* d_out, int out_size)
{
    const int*   tokens  = (const int*)d_in[0];
    const float* embed   = (const float*)d_in[2];
    const float* W_in_w  = (const float*)d_in[3];
    const float* W_in_b  = (const float*)d_in[4];
    const float* left_w  = (const float*)d_in[5];
    const float* left_b  = (const float*)d_in[6];
    const float* right_w = (const float*)d_in[7];
    const float* track_w = (const float*)d_in[8];
    const float* w_ih    = (const float*)d_in[9];
    const float* w_hh    = (const float*)d_in[10];
    const float* b_ih    = (const float*)d_in[11];
    const float* b_hh    = (const float*)d_in[12];
    const float* Wout    = (const float*)d_in[13];
    const float* bout    = (const float*)d_in[14];
    float* out = (float*)d_out;
    (void)in_sizes; (void)n_in; (void)out_size;

    float *buf, *bufR, *embedR, *P12, *P3, *Prw, *Plw;
    float *Wc12, *W3i, *Rw, *Lw, *Win;
    int* cmap;
    cudaGetSymbolAddress((void**)&buf,    g_buf);
    cudaGetSymbolAddress((void**)&bufR,   g_bufR);
    cudaGetSymbolAddress((void**)&embedR, g_embedR);
    cudaGetSymbolAddress((void**)&P12,    g_P12);
    cudaGetSymbolAddress((void**)&P3,     g_P3);
    cudaGetSymbolAddress((void**)&Prw,    g_Prw);
    cudaGetSymbolAddress((void**)&Plw,    g_Plw);
    cudaGetSymbolAddress((void**)&Wc12,   g_Wc12);
    cudaGetSymbolAddress((void**)&W3i,    g_W3i);
    cudaGetSymbolAddress((void**)&Rw,     g_Rw);
    cudaGetSymbolAddress((void**)&Lw,     g_Lw);
    cudaGetSymbolAddress((void**)&Win,    g_Win);
    cudaGetSymbolAddress((void**)&cmap,   g_cmap);

    cudaFuncSetAttribute((const void*)tgemm<1, 1>, cudaFuncAttributeMaxDynamicSharedMemorySize, SMEMB);
    cudaFuncSetAttribute((const void*)tgemm<2, 0>, cudaFuncAttributeMaxDynamicSharedMemorySize, SMEMB);
    cudaFuncSetAttribute((const void*)persist_k,   cudaFuncAttributeMaxDynamicSharedMemorySize, SMEMB);

    // 1) pack + round + metadata
    pack_k<<<2560, 256>>>(w_ih, w_hh, b_ih, b_hh, left_w, right_w, track_w, W_in_w);
    round_embed_k<<<50000, 256>>>(embed);
    init_meta_k<<<1, 1>>>();
    reset_bar_k<<<1, 1>>>();

    // 2) buf = selu(embed[tokens] @ Win^T + b); dual write full + rounded
    tgemm<1, 1><<<dim3(4, 2032), 128, SMEMB>>>(
        8, Win, buf, 256, W_in_b, nullptr, 0, nullptr, 0,
        nullptr, bufR, nullptr,
        embedR, 0, nullptr, 0, tokens, 0);

    // 3) outputs0
    out0_k<<<(B_ * NTR_ * 32) / 256, 256>>>(buf, Wout, bout, out);

    // 4) parallel precomputes
    tgemm<2, 0><<<dim3(32, 1056), 128, SMEMB>>>(
        8, Wc12, P12, 2048, nullptr, nullptr, 0, nullptr, 0,
        nullptr, nullptr, nullptr, bufR, 0, nullptr, 0, cmap, 66);
    tgemm<2, 0><<<dim3(16, 48), 128, SMEMB>>>(
        8, W3i, P3, 1024, nullptr, nullptr, 0, nullptr, 0,
        nullptr, nullptr, nullptr, bufR, 0, nullptr, 0, cmap + 66, 3);
    tgemm<2, 0><<<dim3(20, 992), 128, SMEMB>>>(
        8, Rw, Prw, 1280, nullptr, nullptr, 0, nullptr, 0,
        nullptr, nullptr, nullptr, bufR, 0, nullptr, 0, cmap + 69, 62);
    tgemm<2, 0><<<dim3(20, 16), 128, SMEMB>>>(
        8, Lw, Plw, 1280, nullptr, nullptr, 0, nullptr, 0,
        nullptr, nullptr, nullptr, bufR, 0, nullptr, 0, cmap + 131, 1);

    // 5) entire sequential chain in ONE persistent kernel
    persist_k<<<G_, 256, SMEMB>>>(out, left_b, Wout, bout);
}